// round 11
// baseline (speedup 1.0000x reference)
#include <cuda_runtime.h>
#include <math.h>
#include <stdint.h>

#define SS 512
#define BB 64
#define II 1024
#define HH 1024
#define SB (SS*BB)

// ---------------- scratch (static device globals; no allocation) -------------
__device__ float g_XP[4ULL * SB * HH];          // input projections [4][S*B][H]
__device__ float g_Hall[(size_t)SB * HH];       // h_t row-major (tf32-rounded)
__device__ float g_HTp[2][HH * BB];             // h transposed+pair-packed, ping-pong
__device__ float g_Wpk[128ULL * 128 * 32 * 8];  // packed recurrent weights
__device__ float g_Xr[(size_t)SB * II];         // tf32-rounded x
__device__ float g_Wxr[4ULL * II * HH];         // tf32-rounded input weights
__device__ float g_Whyr[(size_t)HH * HH];       // tf32-rounded output weights
__device__ unsigned g_cnt1[8];                   // barrier level-1 (monotonic)
__device__ unsigned g_cnt2;                      // barrier level-2 (monotonic)
__device__ volatile unsigned g_go;               // release flag

// ---------------- helpers ----------------------------------------------------
__device__ __forceinline__ float f2tf32(float f) {
    uint32_t r;
    asm("cvt.rna.tf32.f32 %0, %1;" : "=r"(r) : "f"(f));
    return __uint_as_float(r);
}

__device__ __forceinline__ void mma_tf32(float c[4], const uint32_t a[4], const uint32_t b[2]) {
    asm volatile(
        "mma.sync.aligned.m16n8k8.row.col.f32.tf32.tf32.f32 "
        "{%0,%1,%2,%3}, {%4,%5,%6,%7}, {%8,%9}, {%0,%1,%2,%3};"
        : "+f"(c[0]), "+f"(c[1]), "+f"(c[2]), "+f"(c[3])
        : "r"(a[0]), "r"(a[1]), "r"(a[2]), "r"(a[3]), "r"(b[0]), "r"(b[1]));
}

__device__ __forceinline__ void cp_async16(uint32_t dst_smem, const void* src) {
    asm volatile("cp.async.cg.shared.global [%0], [%1], 16;" :: "r"(dst_smem), "l"(src));
}
__device__ __forceinline__ void cp_commit() { asm volatile("cp.async.commit_group;"); }
template<int N> __device__ __forceinline__ void cp_wait() {
    asm volatile("cp.async.wait_group %0;" :: "n"(N));
}

// ---------------- init / repack ----------------------------------------------
__global__ void init_state_kernel() {
    int idx = blockIdx.x * blockDim.x + threadIdx.x;
    if (idx < BB * HH) g_HTp[0][idx] = 0.0f;
    if (idx < 8) g_cnt1[idx] = 0u;
    if (idx == 8) g_cnt2 = 0u;
    if (idx == 9) g_go = 0u;
}

__global__ __launch_bounds__(256) void repack_w(
    const float* __restrict__ Wi, const float* __restrict__ Wf,
    const float* __restrict__ Wc, const float* __restrict__ Wo)
{
    const float* W[4] = {Wi, Wf, Wc, Wo};
    int n = blockIdx.x * blockDim.x + threadIdx.x;
    int hi   = n & 1;
    int p    = (n >> 1) & 3;
    int pcol = (n >> 3) & 31;
    int k8   = (n >> 8) & 127;
    int bx   = n >> 15;
    int gate = pcol >> 3;
    int col  = bx * 8 + (pcol & 7);
    int k    = k8 * 8 + p + hi * 4;
    g_Wpk[n] = f2tf32(W[gate][(size_t)k * HH + col]);
}

__global__ __launch_bounds__(256) void round_x(const float* __restrict__ x) {
    size_t i = (size_t)blockIdx.x * 256 + threadIdx.x;
    g_Xr[i] = f2tf32(x[i]);
}
__global__ __launch_bounds__(256) void round_wx(
    const float* __restrict__ W0, const float* __restrict__ W1,
    const float* __restrict__ W2, const float* __restrict__ W3)
{
    const float* W[4] = {W0, W1, W2, W3};
    size_t i = (size_t)blockIdx.x * 256 + threadIdx.x;
    int g = (int)(i >> 20);
    g_Wxr[i] = f2tf32(W[g][i & 0xFFFFF]);
}
__global__ __launch_bounds__(256) void round_why(const float* __restrict__ Why) {
    size_t i = (size_t)blockIdx.x * 256 + threadIdx.x;
    g_Whyr[i] = f2tf32(Why[i]);
}

// ---------------- big tf32 GEMM, cp.async 3-stage ----------------------------
#define GAS 4608   // A stage: 128*36
#define GBS 4224   // B stage: 32*132
#define GST 3

__device__ __forceinline__ void gemm_async_core(
    const float* __restrict__ A, const float* __restrict__ Bw,
    const float* __restrict__ bias, float* __restrict__ C)
{
    extern __shared__ __align__(16) float gsm[];
    float* Asm = gsm;                 // 3 * 4608
    float* Bsm = gsm + GST * GAS;     // 3 * 4224

    const int tid  = threadIdx.x;
    const int lane = tid & 31;
    const int w    = tid >> 5;
    const int wm   = w & 1;
    const int wn   = w >> 1;
    const int m0   = blockIdx.y * 128;
    const int n0   = blockIdx.x * 128;

    const uint32_t sA = (uint32_t)__cvta_generic_to_shared(Asm);
    const uint32_t sB = (uint32_t)__cvta_generic_to_shared(Bsm);

    float acc[4][4][4];
    #pragma unroll
    for (int i = 0; i < 4; ++i)
        #pragma unroll
        for (int j = 0; j < 4; ++j)
            #pragma unroll
            for (int r = 0; r < 4; ++r) acc[i][j][r] = 0.0f;

    auto issue = [&](int it, int slot) {
        int k0 = it * 32;
        #pragma unroll
        for (int j = 0; j < 4; ++j) {
            int idx = tid + 256 * j;          // 0..1023
            int ar = idx >> 3, akc = (idx & 7) * 4;
            cp_async16(sA + (slot * GAS + ar * 36 + akc) * 4,
                       A + (size_t)(m0 + ar) * II + k0 + akc);
            int bk = idx >> 5, bnc = (idx & 31) * 4;
            cp_async16(sB + (slot * GBS + bk * 132 + bnc) * 4,
                       Bw + (size_t)(k0 + bk) * HH + n0 + bnc);
        }
    };

    issue(0, 0); cp_commit();
    issue(1, 1); cp_commit();

    for (int it = 0; it < 32; ++it) {
        cp_wait<1>();
        __syncthreads();
        if (it + 2 < 32) issue(it + 2, (it + 2) % GST);
        cp_commit();

        const float* As = Asm + (it % GST) * GAS;
        const float* Bs = Bsm + (it % GST) * GBS;

        #pragma unroll
        for (int kk = 0; kk < 4; ++kk) {
            const int kb = kk * 8;
            uint32_t af[4][4], bf[4][2];
            #pragma unroll
            for (int mt = 0; mt < 4; ++mt) {
                int r = wm * 64 + mt * 16 + (lane >> 2);
                int c = kb + (lane & 3);
                af[mt][0] = __float_as_uint(As[r * 36 + c]);
                af[mt][1] = __float_as_uint(As[(r + 8) * 36 + c]);
                af[mt][2] = __float_as_uint(As[r * 36 + c + 4]);
                af[mt][3] = __float_as_uint(As[(r + 8) * 36 + c + 4]);
            }
            #pragma unroll
            for (int nt = 0; nt < 4; ++nt) {
                int n = wn * 32 + nt * 8 + (lane >> 2);
                bf[nt][0] = __float_as_uint(Bs[(kb + (lane & 3)) * 132 + n]);
                bf[nt][1] = __float_as_uint(Bs[(kb + 4 + (lane & 3)) * 132 + n]);
            }
            #pragma unroll
            for (int mt = 0; mt < 4; ++mt)
                #pragma unroll
                for (int nt = 0; nt < 4; ++nt)
                    mma_tf32(acc[mt][nt], af[mt], bf[nt]);
        }
    }

    #pragma unroll
    for (int mt = 0; mt < 4; ++mt) {
        int row = m0 + wm * 64 + mt * 16 + (lane >> 2);
        #pragma unroll
        for (int nt = 0; nt < 4; ++nt) {
            int col = n0 + wn * 32 + nt * 8 + 2 * (lane & 3);
            float b0 = bias[col], b1 = bias[col + 1];
            float2 v0 = {acc[mt][nt][0] + b0, acc[mt][nt][1] + b1};
            float2 v1 = {acc[mt][nt][2] + b0, acc[mt][nt][3] + b1};
            *(float2*)&C[(size_t)row * HH + col]       = v0;
            *(float2*)&C[(size_t)(row + 8) * HH + col] = v1;
        }
    }
}

// Wrappers: device globals bound in DEVICE code only.
__global__ __launch_bounds__(256) void gemm_xproj_async(
    const float* __restrict__ b0, const float* __restrict__ b1,
    const float* __restrict__ b2, const float* __restrict__ b3)
{
    const float* bs[4] = {b0, b1, b2, b3};
    int g = blockIdx.z;
    gemm_async_core(g_Xr, g_Wxr + (size_t)g * II * HH, bs[g],
                    g_XP + (size_t)g * SB * HH);
}

__global__ __launch_bounds__(256) void gemm_outproj_async(
    const float* __restrict__ bias, float* __restrict__ out)
{
    gemm_async_core(g_Hall, g_Whyr, bias, out);
}

// ---------------- Persistent recurrence kernel -------------------------------
// 128 blocks x 512 threads (16 warps), 1 block/SM.
// Block bx: hidden cols [bx*8,bx*8+8) x 4 gates = 32 pre-cols, 64 batch rows.
// BK=64 stages (16 iterations), 4-stage cp.async pipeline.
// Warps: 4 m-tiles (wm) x 4 k-groups (wk); each warp handles chunks {wk,wk+4}
// of each stage (2 A-frags, 8 MMAs per iter). 4-way k-reduction via smem.
// Fast two-level grid barrier with release flag.
// smem: W 32768 | A 4*4096 (alias red 3*2176) | XP 2*2048 | pre 2176 = 216.5KB
#define PST 4
#define PNIT 16
#define REDW 2176   // 64*34

__global__ __launch_bounds__(512) void lstm_persist(
    const float* __restrict__ bi, const float* __restrict__ bf,
    const float* __restrict__ bc, const float* __restrict__ bo)
{
    extern __shared__ __align__(16) float sm[];
    float* Wsm  = sm;                              // 32768
    float* Asm  = sm + 32768;                      // 4*4096 (alias red 3*2176)
    float* XPsm = Asm + PST * 4096;                // 2*2048
    float* pre  = XPsm + 4096;                     // 2176

    const int tid  = threadIdx.x;
    const int lane = tid & 31;
    const int w    = tid >> 5;
    const int wm   = w & 3;        // m-tile (16 rows)
    const int wk   = w >> 2;       // k-group (chunks wk, wk+4 of each stage)
    const int bx   = blockIdx.x;
    const int c0   = bx * 8;

    const uint32_t sW = (uint32_t)__cvta_generic_to_shared(Wsm);
    const uint32_t sA = (uint32_t)__cvta_generic_to_shared(Asm);
    const uint32_t sX = (uint32_t)__cvta_generic_to_shared(XPsm);

    // ---- load weights once ----
    {
        const float* Wsrc = g_Wpk + (size_t)bx * 32768;
        #pragma unroll 4
        for (int j = 0; j < 16; ++j) {
            int idx = tid + 512 * j;
            cp_async16(sW + idx * 16, Wsrc + idx * 4);
        }
    }
    // ---- XP prefetch for step 0 ----
    {
        int gate = tid >> 7, r2 = (tid >> 1) & 63, half = tid & 1;
        const float* src = g_XP + (size_t)gate * SB * HH
                         + (size_t)r2 * HH + c0 + half * 4;
        cp_async16(sX + (gate * 512 + r2 * 8 + half * 4) * 4, src);
    }
    cp_commit();

    // per-thread epilogue constants
    const int cc  = tid & 7;
    const int col = c0 + cc;
    const int row = tid >> 3;            // 0..63
    const float bI = bi[col], bF = bf[col], bC = bc[col], bO = bo[col];
    float creg = 0.0f;

    for (int t = 0; t < SS; ++t) {
        const float* Asrc = g_HTp[t & 1];
        float*       hout = g_Hall + (size_t)t * BB * HH;
        float*       hTn  = g_HTp[(t + 1) & 1];

        float acc[4][4];     // [nt][r], partial over chunks {wk, wk+4}
        #pragma unroll
        for (int nt = 0; nt < 4; ++nt)
            #pragma unroll
            for (int r = 0; r < 4; ++r) acc[nt][r] = 0.0f;

        // prologue: 3 stages (BK=64 each: 4096 floats, 2x16B per thread)
        #pragma unroll
        for (int i = 0; i < PST - 1; ++i) {
            cp_async16(sA + ((i % PST) * 4096 + tid * 8) * 4,
                       Asrc + i * 4096 + tid * 8);
            cp_async16(sA + ((i % PST) * 4096 + tid * 8 + 4) * 4,
                       Asrc + i * 4096 + tid * 8 + 4);
            cp_commit();
        }

        for (int it = 0; it < PNIT; ++it) {
            cp_wait<PST - 2>();
            __syncthreads();
            if (it + PST - 1 < PNIT) {
                int i = it + PST - 1;
                cp_async16(sA + ((i % PST) * 4096 + tid * 8) * 4,
                           Asrc + i * 4096 + tid * 8);
                cp_async16(sA + ((i % PST) * 4096 + tid * 8 + 4) * 4,
                           Asrc + i * 4096 + tid * 8 + 4);
            }
            if (it == 0 && t + 1 < SS) {
                int buf  = (t + 1) & 1;
                int gate = tid >> 7, r2 = (tid >> 1) & 63, half = tid & 1;
                const float* src = g_XP + (size_t)gate * SB * HH
                                 + ((size_t)(t + 1) * BB + r2) * HH + c0 + half * 4;
                cp_async16(sX + (buf * 2048 + gate * 512 + r2 * 8 + half * 4) * 4, src);
            }
            cp_commit();

            const float* Asl = Asm + (it % PST) * 4096;
            const float* Bsl = Wsm + it * 2048;

            #pragma unroll
            for (int h = 0; h < 2; ++h) {
                const int chunk = wk + h * 4;     // 0..7 within stage
                uint32_t af[4];
                {
                    int base = chunk * 512 + (wm * 16 + (lane >> 2)) * 8 + (lane & 3) * 2;
                    float2 a0 = *(const float2*)(Asl + base);
                    float2 a1 = *(const float2*)(Asl + base + 64);
                    af[0] = __float_as_uint(a0.x);
                    af[1] = __float_as_uint(a1.x);
                    af[2] = __float_as_uint(a0.y);
                    af[3] = __float_as_uint(a1.y);
                }
                #pragma unroll
                for (int nt = 0; nt < 4; ++nt) {
                    int pb = chunk * 256 + (nt * 8 + (lane >> 2)) * 8 + (lane & 3) * 2;
                    float2 b = *(const float2*)(Bsl + pb);
                    uint32_t bfr[2] = {__float_as_uint(b.x), __float_as_uint(b.y)};
                    mma_tf32(acc[nt], af, bfr);
                }
            }
        }

        cp_wait<0>();
        __syncthreads();

        // ---- 4-way k reduction (red aliases Asm; stride 34 keeps float2 aligned) ----
        float* red = Asm;   // red[3][64][34]
        if (wk > 0) {
            #pragma unroll
            for (int nt = 0; nt < 4; ++nt) {
                int r0 = wm * 16 + (lane >> 2);
                int cr = nt * 8 + 2 * (lane & 3);
                *(float2*)&red[(wk - 1) * REDW + r0 * 34 + cr]
                    = make_float2(acc[nt][0], acc[nt][1]);
                *(float2*)&red[(wk - 1) * REDW + (r0 + 8) * 34 + cr]
                    = make_float2(acc[nt][2], acc[nt][3]);
            }
        }
        __syncthreads();
        if (wk == 0) {
            #pragma unroll
            for (int nt = 0; nt < 4; ++nt) {
                int r0 = wm * 16 + (lane >> 2);
                int cr = nt * 8 + 2 * (lane & 3);
                float2 s0 = make_float2(acc[nt][0], acc[nt][1]);
                float2 s1 = make_float2(acc[nt][2], acc[nt][3]);
                #pragma unroll
                for (int p = 0; p < 3; ++p) {
                    float2 u0 = *(const float2*)&red[p * REDW + r0 * 34 + cr];
                    float2 u1 = *(const float2*)&red[p * REDW + (r0 + 8) * 34 + cr];
                    s0.x += u0.x; s0.y += u0.y;
                    s1.x += u1.x; s1.y += u1.y;
                }
                *(float2*)&pre[r0 * 34 + cr]       = s0;
                *(float2*)&pre[(r0 + 8) * 34 + cr] = s1;
            }
        }
        __syncthreads();

        // ---- fused elementwise epilogue: 1 element/thread ----
        const float* xp = XPsm + (t & 1) * 2048;
        {
            size_t off = (size_t)row * HH + col;
            int b0 = row * 34 + cc;

            float pi = pre[b0]      + xp[0 * 512 + row * 8 + cc] + bI;
            float pf = pre[b0 + 8]  + xp[1 * 512 + row * 8 + cc] + bF;
            float pc = pre[b0 + 16] + xp[2 * 512 + row * 8 + cc] + bC;
            float po = pre[b0 + 24] + xp[3 * 512 + row * 8 + cc] + bO;

            float iv = 1.0f / (1.0f + expf(-pi));
            float fv = 1.0f / (1.0f + expf(-pf));
            float ov = 1.0f / (1.0f + expf(-po));
            float gv = tanhf(pc);

            float cv = fv * creg + iv * gv;
            float hv = ov * tanhf(cv);
            creg = cv;

            float hr = f2tf32(hv);
            hout[off] = hr;
            hTn[((bx * 64 + row) << 3) + ((col & 3) << 1) + ((col >> 2) & 1)] = hr;
        }

        // ---- fast two-level grid barrier ----
        if (t + 1 < SS) {
            __threadfence();
            __syncthreads();
            if (tid == 0) {
                unsigned r = atomicAdd(&g_cnt1[bx & 7], 1u);
                if (r == (unsigned)(t * 16 + 15)) {          // last of this group
                    unsigned r2 = atomicAdd(&g_cnt2, 1u);
                    if (r2 == (unsigned)(t * 8 + 7)) {       // last group
                        atomicExch((unsigned*)&g_go, (unsigned)(t + 1));
                    }
                }
                while (g_go < (unsigned)(t + 1)) { __nanosleep(16); }
            }
            __syncthreads();
        }
    }
}

// ---------------- launch -----------------------------------------------------
extern "C" void kernel_launch(void* const* d_in, const int* in_sizes, int n_in,
                              void* d_out, int out_size)
{
    (void)in_sizes; (void)n_in; (void)out_size;

    const float* x    = (const float*)d_in[0];
    const float* Wx[4] = {(const float*)d_in[1], (const float*)d_in[3],
                          (const float*)d_in[5], (const float*)d_in[7]};
    const float* bx[4] = {(const float*)d_in[2], (const float*)d_in[4],
                          (const float*)d_in[6], (const float*)d_in[8]};
    const float* Wh[4] = {(const float*)d_in[9],  (const float*)d_in[11],
                          (const float*)d_in[13], (const float*)d_in[15]};
    const float* bh[4] = {(const float*)d_in[10], (const float*)d_in[12],
                          (const float*)d_in[14], (const float*)d_in[16]};
    const float* Why = (const float*)d_in[17];
    const float* bhy = (const float*)d_in[18];
    float* out = (float*)d_out;

    static int smem_set = 0;
    const int psmem = (32768 + PST * 4096 + 2 * 2048 + REDW) * 4;
    const int gsmem = GST * (GAS + GBS) * 4;
    if (!smem_set) {
        cudaFuncSetAttribute(lstm_persist,
                             cudaFuncAttributeMaxDynamicSharedMemorySize, psmem);
        cudaFuncSetAttribute(gemm_xproj_async,
                             cudaFuncAttributeMaxDynamicSharedMemorySize, gsmem);
        cudaFuncSetAttribute(gemm_outproj_async,
                             cudaFuncAttributeMaxDynamicSharedMemorySize, gsmem);
        smem_set = 1;
    }

    init_state_kernel<<<(BB * HH + 255) / 256, 256>>>();
    repack_w<<<(128 * 128 * 32 * 8) / 256, 256>>>(Wh[0], Wh[1], Wh[2], Wh[3]);
    round_x<<<(int)(((size_t)SB * II) / 256), 256>>>(x);
    round_wx<<<(4 * II * HH) / 256, 256>>>(Wx[0], Wx[1], Wx[2], Wx[3]);
    round_why<<<(II * HH) / 256, 256>>>(Why);

    // input projections: XP[g] = x @ W_x[g] + b_x[g]  (one launch, z=4)
    {
        dim3 grid(HH / 128, SB / 128, 4);
        gemm_xproj_async<<<grid, 256, gsmem>>>(bx[0], bx[1], bx[2], bx[3]);
    }

    lstm_persist<<<128, 512, psmem>>>(bh[0], bh[1], bh[2], bh[3]);

    // output projection: Y = H_all @ W_hy + b_hy
    {
        dim3 grid(HH / 128, SB / 128);
        gemm_outproj_async<<<grid, 256, gsmem>>>(bhy, out);
    }
}

// round 13
// speedup vs baseline: 1.2378x; 1.2378x over previous
#include <cuda_runtime.h>
#include <cuda_fp16.h>
#include <math.h>
#include <stdint.h>

#define SS 512
#define BB 64
#define II 1024
#define HH 1024
#define SB (SS*BB)

// ---------------- scratch (static device globals; no allocation) -------------
__device__ float    g_XP[4ULL * SB * HH];        // input projections [4][S*B][H]
__device__ float    g_Hall[(size_t)SB * HH];     // h_t row-major (tf32-rounded)
__device__ uint32_t g_HTp16[2][32768];           // h fp16 fragment-packed, ping-pong (128KB each)
__device__ uint32_t g_Wpk16[128ULL * 16384];     // fp16 packed recurrent weights (64KB/block)
__device__ float    g_Xr[(size_t)SB * II];       // tf32-rounded x
__device__ float    g_Wxr[4ULL * II * HH];       // tf32-rounded input weights
__device__ float    g_Whyr[(size_t)HH * HH];     // tf32-rounded output weights
__device__ unsigned g_bar;                        // grid barrier (monotonic)

// ---------------- helpers ----------------------------------------------------
__device__ __forceinline__ float f2tf32(float f) {
    uint32_t r;
    asm("cvt.rna.tf32.f32 %0, %1;" : "=r"(r) : "f"(f));
    return __uint_as_float(r);
}

__device__ __forceinline__ void mma_tf32(float c[4], const uint32_t a[4], const uint32_t b[2]) {
    asm volatile(
        "mma.sync.aligned.m16n8k8.row.col.f32.tf32.tf32.f32 "
        "{%0,%1,%2,%3}, {%4,%5,%6,%7}, {%8,%9}, {%0,%1,%2,%3};"
        : "+f"(c[0]), "+f"(c[1]), "+f"(c[2]), "+f"(c[3])
        : "r"(a[0]), "r"(a[1]), "r"(a[2]), "r"(a[3]), "r"(b[0]), "r"(b[1]));
}

__device__ __forceinline__ void mma_f16(float c[4], uint32_t a0, uint32_t a1,
                                        uint32_t a2, uint32_t a3,
                                        uint32_t b0, uint32_t b1) {
    asm volatile(
        "mma.sync.aligned.m16n8k16.row.col.f32.f16.f16.f32 "
        "{%0,%1,%2,%3}, {%4,%5,%6,%7}, {%8,%9}, {%0,%1,%2,%3};"
        : "+f"(c[0]), "+f"(c[1]), "+f"(c[2]), "+f"(c[3])
        : "r"(a0), "r"(a1), "r"(a2), "r"(a3), "r"(b0), "r"(b1));
}

__device__ __forceinline__ void cp_async16(uint32_t dst_smem, const void* src) {
    asm volatile("cp.async.cg.shared.global [%0], [%1], 16;" :: "r"(dst_smem), "l"(src));
}
__device__ __forceinline__ void cp_commit() { asm volatile("cp.async.commit_group;"); }
template<int N> __device__ __forceinline__ void cp_wait() {
    asm volatile("cp.async.wait_group %0;" :: "n"(N));
}

// ---------------- init / repack ----------------------------------------------
__global__ void init_state_kernel() {
    int idx = blockIdx.x * blockDim.x + threadIdx.x;
    if (idx < 32768) g_HTp16[0][idx] = 0u;
    if (idx == 32768) g_bar = 0u;
}

// fp16 fragment-order weight repack:
// half index n = ((((bx*64+chunk)*32+pcol)*4+c)*2+p)*2+d
//   k = chunk*16 + 2c + d + 8p, gate = pcol>>3, col = bx*8 + (pcol&7)
__global__ __launch_bounds__(256) void repack_w16(
    const float* __restrict__ Wi, const float* __restrict__ Wf,
    const float* __restrict__ Wc, const float* __restrict__ Wo)
{
    const float* W[4] = {Wi, Wf, Wc, Wo};
    int n = blockIdx.x * blockDim.x + threadIdx.x;   // 0 .. 4194303
    int d     = n & 1;
    int p     = (n >> 1) & 1;
    int c     = (n >> 2) & 3;
    int pcol  = (n >> 4) & 31;
    int chunk = (n >> 9) & 63;
    int bx    = n >> 15;
    int gate  = pcol >> 3;
    int col   = bx * 8 + (pcol & 7);
    int k     = chunk * 16 + 2 * c + d + 8 * p;
    ((__half*)g_Wpk16)[n] = __float2half(W[gate][(size_t)k * HH + col]);
}

__global__ __launch_bounds__(256) void round_x(const float* __restrict__ x) {
    size_t i = (size_t)blockIdx.x * 256 + threadIdx.x;
    g_Xr[i] = f2tf32(x[i]);
}
__global__ __launch_bounds__(256) void round_wx(
    const float* __restrict__ W0, const float* __restrict__ W1,
    const float* __restrict__ W2, const float* __restrict__ W3)
{
    const float* W[4] = {W0, W1, W2, W3};
    size_t i = (size_t)blockIdx.x * 256 + threadIdx.x;
    int g = (int)(i >> 20);
    g_Wxr[i] = f2tf32(W[g][i & 0xFFFFF]);
}
__global__ __launch_bounds__(256) void round_why(const float* __restrict__ Why) {
    size_t i = (size_t)blockIdx.x * 256 + threadIdx.x;
    g_Whyr[i] = f2tf32(Why[i]);
}

// ---------------- big tf32 GEMM, cp.async 3-stage (unchanged, known-good) ----
#define GAS 4608   // A stage: 128*36
#define GBS 4224   // B stage: 32*132
#define GST 3

__device__ __forceinline__ void gemm_async_core(
    const float* __restrict__ A, const float* __restrict__ Bw,
    const float* __restrict__ bias, float* __restrict__ C)
{
    extern __shared__ __align__(16) float gsm[];
    float* Asm = gsm;
    float* Bsm = gsm + GST * GAS;

    const int tid  = threadIdx.x;
    const int lane = tid & 31;
    const int w    = tid >> 5;
    const int wm   = w & 1;
    const int wn   = w >> 1;
    const int m0   = blockIdx.y * 128;
    const int n0   = blockIdx.x * 128;

    const uint32_t sA = (uint32_t)__cvta_generic_to_shared(Asm);
    const uint32_t sB = (uint32_t)__cvta_generic_to_shared(Bsm);

    float acc[4][4][4];
    #pragma unroll
    for (int i = 0; i < 4; ++i)
        #pragma unroll
        for (int j = 0; j < 4; ++j)
            #pragma unroll
            for (int r = 0; r < 4; ++r) acc[i][j][r] = 0.0f;

    auto issue = [&](int it, int slot) {
        int k0 = it * 32;
        #pragma unroll
        for (int j = 0; j < 4; ++j) {
            int idx = tid + 256 * j;
            int ar = idx >> 3, akc = (idx & 7) * 4;
            cp_async16(sA + (slot * GAS + ar * 36 + akc) * 4,
                       A + (size_t)(m0 + ar) * II + k0 + akc);
            int bk = idx >> 5, bnc = (idx & 31) * 4;
            cp_async16(sB + (slot * GBS + bk * 132 + bnc) * 4,
                       Bw + (size_t)(k0 + bk) * HH + n0 + bnc);
        }
    };

    issue(0, 0); cp_commit();
    issue(1, 1); cp_commit();

    for (int it = 0; it < 32; ++it) {
        cp_wait<1>();
        __syncthreads();
        if (it + 2 < 32) issue(it + 2, (it + 2) % GST);
        cp_commit();

        const float* As = Asm + (it % GST) * GAS;
        const float* Bs = Bsm + (it % GST) * GBS;

        #pragma unroll
        for (int kk = 0; kk < 4; ++kk) {
            const int kb = kk * 8;
            uint32_t af[4][4], bf[4][2];
            #pragma unroll
            for (int mt = 0; mt < 4; ++mt) {
                int r = wm * 64 + mt * 16 + (lane >> 2);
                int c = kb + (lane & 3);
                af[mt][0] = __float_as_uint(As[r * 36 + c]);
                af[mt][1] = __float_as_uint(As[(r + 8) * 36 + c]);
                af[mt][2] = __float_as_uint(As[r * 36 + c + 4]);
                af[mt][3] = __float_as_uint(As[(r + 8) * 36 + c + 4]);
            }
            #pragma unroll
            for (int nt = 0; nt < 4; ++nt) {
                int n = wn * 32 + nt * 8 + (lane >> 2);
                bf[nt][0] = __float_as_uint(Bs[(kb + (lane & 3)) * 132 + n]);
                bf[nt][1] = __float_as_uint(Bs[(kb + 4 + (lane & 3)) * 132 + n]);
            }
            #pragma unroll
            for (int mt = 0; mt < 4; ++mt)
                #pragma unroll
                for (int nt = 0; nt < 4; ++nt)
                    mma_tf32(acc[mt][nt], af[mt], bf[nt]);
        }
    }

    #pragma unroll
    for (int mt = 0; mt < 4; ++mt) {
        int row = m0 + wm * 64 + mt * 16 + (lane >> 2);
        #pragma unroll
        for (int nt = 0; nt < 4; ++nt) {
            int col = n0 + wn * 32 + nt * 8 + 2 * (lane & 3);
            float b0 = bias[col], b1 = bias[col + 1];
            float2 v0 = {acc[mt][nt][0] + b0, acc[mt][nt][1] + b1};
            float2 v1 = {acc[mt][nt][2] + b0, acc[mt][nt][3] + b1};
            *(float2*)&C[(size_t)row * HH + col]       = v0;
            *(float2*)&C[(size_t)(row + 8) * HH + col] = v1;
        }
    }
}

__global__ __launch_bounds__(256) void gemm_xproj_async(
    const float* __restrict__ b0, const float* __restrict__ b1,
    const float* __restrict__ b2, const float* __restrict__ b3)
{
    const float* bs[4] = {b0, b1, b2, b3};
    int g = blockIdx.z;
    gemm_async_core(g_Xr, g_Wxr + (size_t)g * II * HH, bs[g],
                    g_XP + (size_t)g * SB * HH);
}

__global__ __launch_bounds__(256) void gemm_outproj_async(
    const float* __restrict__ bias, float* __restrict__ out)
{
    gemm_async_core(g_Hall, g_Whyr, bias, out);
}

// ---------------- Persistent recurrence kernel (fp16 MMA) --------------------
// 128 blocks x 512 threads (16 warps), 1 block/SM.
// Block bx: hidden cols [bx*8,bx*8+8) x 4 gates = 32 pre-cols, 64 batch rows.
// K=1024 = 16 stages x 64; stage = 4 k16-chunks. Warps: 4 m-tiles (wm) x
// 4 chunk-slots (wk). Per iter/warp: 2 LDS.64 (A) + 4 LDS.64 (B) + 4 fp16 MMAs.
// 4-way k-reduction via smem (aliases drained A stages, stride 34).
// smem(u32/f32 units): W 16384 | A 6*2048 (alias red 3*2176f) | XP 2*2048f | pre 2176f
#define PST 6
#define PNIT 16
#define REDW 2176   // 64*34

__global__ __launch_bounds__(512) void lstm_persist(
    const float* __restrict__ bi, const float* __restrict__ bf,
    const float* __restrict__ bc, const float* __restrict__ bo)
{
    extern __shared__ __align__(16) uint32_t smu[];
    uint32_t* Wsm16 = smu;                         // 16384 u32 (64KB)
    uint32_t* Asm32 = smu + 16384;                 // 6*2048 u32 (48KB, alias red)
    float*    XPsm  = (float*)(smu + 16384 + PST * 2048);  // 2*2048 f
    float*    pre   = XPsm + 4096;                 // 2176 f
    float*    red   = (float*)Asm32;               // red[3][64][34]

    const int tid  = threadIdx.x;
    const int lane = tid & 31;
    const int w    = tid >> 5;
    const int wm   = w & 3;        // m-tile (16 rows)
    const int wk   = w >> 2;       // chunk slot within stage
    const int bx   = blockIdx.x;
    const int c0   = bx * 8;

    const uint32_t sW = (uint32_t)__cvta_generic_to_shared(Wsm16);
    const uint32_t sA = (uint32_t)__cvta_generic_to_shared(Asm32);
    const uint32_t sX = (uint32_t)__cvta_generic_to_shared(XPsm);

    // ---- load fp16 weights once (16384 u32 = 4096 x 16B) ----
    {
        const uint32_t* Wsrc = g_Wpk16 + (size_t)bx * 16384;
        #pragma unroll 4
        for (int j = 0; j < 8; ++j) {
            int idx = tid + 512 * j;
            cp_async16(sW + idx * 16, Wsrc + idx * 4);
        }
    }
    // ---- XP prefetch for step 0 ----
    {
        int gate = tid >> 7, r2 = (tid >> 1) & 63, half = tid & 1;
        const float* src = g_XP + (size_t)gate * SB * HH
                         + (size_t)r2 * HH + c0 + half * 4;
        cp_async16(sX + (gate * 512 + r2 * 8 + half * 4) * 4, src);
    }
    cp_commit();

    // per-thread epilogue constants
    const int cc  = tid & 7;
    const int col = c0 + cc;
    const int row = tid >> 3;            // 0..63
    const float bI = bi[col], bF = bf[col], bC = bc[col], bO = bo[col];
    // fp16-packed h write index: col -> (chunk, p, c, d)
    const int hchunk = col >> 4;
    const int hkk    = col & 15;
    const int hp     = hkk >> 3;
    const int hc     = (hkk & 7) >> 1;
    const int hd     = hkk & 1;
    const int hidx   = ((hchunk * 64 + row) * 4 + hc) * 4 + hp * 2 + hd;  // half idx
    float creg = 0.0f;

    // A/B fragment LDS bases (u32 indices)
    const int aoff = ((wm * 16 + (lane >> 2)) * 4 + (lane & 3)) * 2 + wk * 512;
    const int nrow = lane >> 2;       // n within tile
    const int bcc  = lane & 3;

    for (int t = 0; t < SS; ++t) {
        const uint32_t* Asrc = g_HTp16[t & 1];
        float*          hout = g_Hall + (size_t)t * BB * HH;
        uint16_t*       hTn  = (uint16_t*)g_HTp16[(t + 1) & 1];

        float acc[4][4];     // [nt][r], partials over chunks ≡ wk (mod 4)
        #pragma unroll
        for (int nt = 0; nt < 4; ++nt)
            #pragma unroll
            for (int r = 0; r < 4; ++r) acc[nt][r] = 0.0f;

        // prologue: stages 0..PST-2 (each 2048 u32 = 8KB, 1 cp16/thread)
        #pragma unroll
        for (int i = 0; i < PST - 1; ++i) {
            cp_async16(sA + ((i % PST) * 2048 + tid * 4) * 4,
                       Asrc + i * 2048 + tid * 4);
            cp_commit();
        }

        for (int it = 0; it < PNIT; ++it) {
            cp_wait<PST - 2>();
            __syncthreads();
            if (it + PST - 1 < PNIT) {
                int i = it + PST - 1;
                cp_async16(sA + ((i % PST) * 2048 + tid * 4) * 4,
                           Asrc + i * 2048 + tid * 4);
            }
            if (it == 0 && t + 1 < SS) {
                int buf  = (t + 1) & 1;
                int gate = tid >> 7, r2 = (tid >> 1) & 63, half = tid & 1;
                const float* src = g_XP + (size_t)gate * SB * HH
                                 + ((size_t)(t + 1) * BB + r2) * HH + c0 + half * 4;
                cp_async16(sX + (buf * 2048 + gate * 512 + r2 * 8 + half * 4) * 4, src);
            }
            cp_commit();

            const uint32_t* Asl = Asm32 + (it % PST) * 2048;
            const int chunk = it * 4 + wk;

            uint2 a01 = *(const uint2*)(Asl + aoff);        // a0, a2
            uint2 a23 = *(const uint2*)(Asl + aoff + 64);   // a1, a3
            #pragma unroll
            for (int nt = 0; nt < 4; ++nt) {
                const uint32_t* Bb = Wsm16 + ((chunk * 32 + nt * 8 + nrow) * 4 + bcc) * 2;
                uint2 b = *(const uint2*)Bb;
                mma_f16(acc[nt], a01.x, a23.x, a01.y, a23.y, b.x, b.y);
            }
        }

        cp_wait<0>();
        __syncthreads();

        // ---- 4-way k reduction (red aliases Asm32) ----
        if (wk > 0) {
            #pragma unroll
            for (int nt = 0; nt < 4; ++nt) {
                int r0 = wm * 16 + (lane >> 2);
                int cr = nt * 8 + 2 * (lane & 3);
                *(float2*)&red[(wk - 1) * REDW + r0 * 34 + cr]
                    = make_float2(acc[nt][0], acc[nt][1]);
                *(float2*)&red[(wk - 1) * REDW + (r0 + 8) * 34 + cr]
                    = make_float2(acc[nt][2], acc[nt][3]);
            }
        }
        __syncthreads();
        if (wk == 0) {
            #pragma unroll
            for (int nt = 0; nt < 4; ++nt) {
                int r0 = wm * 16 + (lane >> 2);
                int cr = nt * 8 + 2 * (lane & 3);
                float2 s0 = make_float2(acc[nt][0], acc[nt][1]);
                float2 s1 = make_float2(acc[nt][2], acc[nt][3]);
                #pragma unroll
                for (int p = 0; p < 3; ++p) {
                    float2 u0 = *(const float2*)&red[p * REDW + r0 * 34 + cr];
                    float2 u1 = *(const float2*)&red[p * REDW + (r0 + 8) * 34 + cr];
                    s0.x += u0.x; s0.y += u0.y;
                    s1.x += u1.x; s1.y += u1.y;
                }
                *(float2*)&pre[r0 * 34 + cr]       = s0;
                *(float2*)&pre[(r0 + 8) * 34 + cr] = s1;
            }
        }
        __syncthreads();

        // ---- fused elementwise epilogue: 1 element/thread ----
        const float* xp = XPsm + (t & 1) * 2048;
        {
            size_t off = (size_t)row * HH + col;
            int b0 = row * 34 + cc;

            float pi = pre[b0]      + xp[0 * 512 + row * 8 + cc] + bI;
            float pf = pre[b0 + 8]  + xp[1 * 512 + row * 8 + cc] + bF;
            float pc = pre[b0 + 16] + xp[2 * 512 + row * 8 + cc] + bC;
            float po = pre[b0 + 24] + xp[3 * 512 + row * 8 + cc] + bO;

            float iv = 1.0f / (1.0f + expf(-pi));
            float fv = 1.0f / (1.0f + expf(-pf));
            float ov = 1.0f / (1.0f + expf(-po));
            float gv = tanhf(pc);

            float cv = fv * creg + iv * gv;
            float hv = ov * tanhf(cv);
            creg = cv;

            hout[off] = f2tf32(hv);                       // tf32 view for outproj
            hTn[hidx] = __half_as_ushort(__float2half(hv)); // fp16 view for recurrence
        }

        // ---- grid barrier (single monotonic counter, R10-proven) ----
        if (t + 1 < SS) {
            __threadfence();
            __syncthreads();
            if (tid == 0) {
                atomicAdd(&g_bar, 1u);
                unsigned need = 128u * (unsigned)(t + 1);
                while (*((volatile unsigned*)&g_bar) < need) { __nanosleep(16); }
            }
            __syncthreads();
        }
    }
}

// ---------------- launch -----------------------------------------------------
extern "C" void kernel_launch(void* const* d_in, const int* in_sizes, int n_in,
                              void* d_out, int out_size)
{
    (void)in_sizes; (void)n_in; (void)out_size;

    const float* x    = (const float*)d_in[0];
    const float* Wx[4] = {(const float*)d_in[1], (const float*)d_in[3],
                          (const float*)d_in[5], (const float*)d_in[7]};
    const float* bx[4] = {(const float*)d_in[2], (const float*)d_in[4],
                          (const float*)d_in[6], (const float*)d_in[8]};
    const float* Wh[4] = {(const float*)d_in[9],  (const float*)d_in[11],
                          (const float*)d_in[13], (const float*)d_in[15]};
    const float* bh[4] = {(const float*)d_in[10], (const float*)d_in[12],
                          (const float*)d_in[14], (const float*)d_in[16]};
    const float* Why = (const float*)d_in[17];
    const float* bhy = (const float*)d_in[18];
    float* out = (float*)d_out;

    static int smem_set = 0;
    const int psmem = (16384 + PST * 2048 + 2 * 2048 + REDW) * 4;
    const int gsmem = GST * (GAS + GBS) * 4;
    if (!smem_set) {
        cudaFuncSetAttribute(lstm_persist,
                             cudaFuncAttributeMaxDynamicSharedMemorySize, psmem);
        cudaFuncSetAttribute(gemm_xproj_async,
                             cudaFuncAttributeMaxDynamicSharedMemorySize, gsmem);
        cudaFuncSetAttribute(gemm_outproj_async,
                             cudaFuncAttributeMaxDynamicSharedMemorySize, gsmem);
        smem_set = 1;
    }

    init_state_kernel<<<(32768 + 256) / 256, 256>>>();
    repack_w16<<<(128 * 16384 * 2) / 256, 256>>>(Wh[0], Wh[1], Wh[2], Wh[3]);
    round_x<<<(int)(((size_t)SB * II) / 256), 256>>>(x);
    round_wx<<<(4 * II * HH) / 256, 256>>>(Wx[0], Wx[1], Wx[2], Wx[3]);
    round_why<<<(II * HH) / 256, 256>>>(Why);

    // input projections: XP[g] = x @ W_x[g] + b_x[g]  (one launch, z=4)
    {
        dim3 grid(HH / 128, SB / 128, 4);
        gemm_xproj_async<<<grid, 256, gsmem>>>(bx[0], bx[1], bx[2], bx[3]);
    }

    lstm_persist<<<128, 512, psmem>>>(bh[0], bh[1], bh[2], bh[3]);

    // output projection: Y = H_all @ W_hy + b_hy
    {
        dim3 grid(HH / 128, SB / 128);
        gemm_outproj_async<<<grid, 256, gsmem>>>(bhy, out);
    }
}

// round 15
// speedup vs baseline: 1.5810x; 1.2773x over previous
#include <cuda_runtime.h>
#include <cuda_fp16.h>
#include <math.h>
#include <stdint.h>

#define SS 512
#define BB 64
#define II 1024
#define HH 1024
#define SB (SS*BB)

// ---------------- scratch (static device globals; no allocation) -------------
__device__ float    g_XP[4ULL * SB * HH];        // input projections [4][S*B][H] fp32
__device__ uint32_t g_X16[16777216];             // x fp16 fragment-packed [256mt][64ch][128r][8]
__device__ uint32_t g_Hl16[16777216];            // h fp16 fragment-packed (outproj A)
__device__ uint32_t g_Wx16[2097152];             // Wx fp16 packed [4g][8cb][64ch][128n][8]
__device__ uint32_t g_Why16[524288];             // Why fp16 packed [8cb][64ch][128n][8]
__device__ uint32_t g_HTp16[2][32768];           // h fp16 fragment-packed ping-pong (recurrence)
__device__ uint32_t g_Wpk16[128ULL * 16384];     // fp16 packed recurrent weights (64KB/block)
__device__ unsigned g_bar;                        // grid barrier (monotonic)

// ---------------- helpers ----------------------------------------------------
__device__ __forceinline__ void mma_f16(float c[4], uint32_t a0, uint32_t a1,
                                        uint32_t a2, uint32_t a3,
                                        uint32_t b0, uint32_t b1) {
    asm volatile(
        "mma.sync.aligned.m16n8k16.row.col.f32.f16.f16.f32 "
        "{%0,%1,%2,%3}, {%4,%5,%6,%7}, {%8,%9}, {%0,%1,%2,%3};"
        : "+f"(c[0]), "+f"(c[1]), "+f"(c[2]), "+f"(c[3])
        : "r"(a0), "r"(a1), "r"(a2), "r"(a3), "r"(b0), "r"(b1));
}

__device__ __forceinline__ void cp_async16(uint32_t dst_smem, const void* src) {
    asm volatile("cp.async.cg.shared.global [%0], [%1], 16;" :: "r"(dst_smem), "l"(src));
}
__device__ __forceinline__ void cp_commit() { asm volatile("cp.async.commit_group;"); }
template<int N> __device__ __forceinline__ void cp_wait() {
    asm volatile("cp.async.wait_group %0;" :: "n"(N));
}

__device__ __forceinline__ uint32_t pack2h(float a, float b) {
    __half2 h = __floats2half2_rn(a, b);
    return *(uint32_t*)&h;
}

// ---------------- init / pack kernels ----------------------------------------
__global__ void init_state_kernel() {
    int idx = blockIdx.x * blockDim.x + threadIdx.x;
    if (idx < 32768) g_HTp16[0][idx] = 0u;
    if (idx == 32768) g_bar = 0u;
}

// recurrence weights: half n = ((((bx*64+chunk)*32+pcol)*4+c)*2+p)*2+d
__global__ __launch_bounds__(256) void repack_w16(
    const float* __restrict__ Wi, const float* __restrict__ Wf,
    const float* __restrict__ Wc, const float* __restrict__ Wo)
{
    const float* W[4] = {Wi, Wf, Wc, Wo};
    int n = blockIdx.x * blockDim.x + threadIdx.x;   // u32 index, 0..2097151
    int p     = n & 1;
    int c     = (n >> 1) & 3;
    int pcol  = (n >> 3) & 31;
    int chunk = (n >> 8) & 63;
    int bx    = n >> 14;
    int gate  = pcol >> 3;
    int col   = bx * 8 + (pcol & 7);
    int k     = chunk * 16 + 2 * c + 8 * p;
    g_Wpk16[n] = pack2h(W[gate][(size_t)k * HH + col],
                        W[gate][(size_t)(k + 1) * HH + col]);
}

// x packed as A-fragments: u32 idx = ((mt*64+ch)*128+row)*8 + c*2 + p
__global__ __launch_bounds__(256) void pack_x(const float* __restrict__ x) {
    int n = blockIdx.x * blockDim.x + threadIdx.x;   // 0..16777215
    int p   = n & 1;
    int c   = (n >> 1) & 3;
    int row = (n >> 3) & 127;
    int ch  = (n >> 10) & 63;
    int mt  = n >> 16;
    size_t R = (size_t)mt * 128 + row;
    int k = ch * 16 + 2 * c + 8 * p;
    const float* src = x + R * II + k;
    g_X16[n] = pack2h(src[0], src[1]);
}

// Wx packed as B-fragments: u32 idx = (((g*8+cb)*64+ch)*128+nn)*8 + c*2 + p
__global__ __launch_bounds__(256) void pack_wx(
    const float* __restrict__ W0, const float* __restrict__ W1,
    const float* __restrict__ W2, const float* __restrict__ W3)
{
    const float* W[4] = {W0, W1, W2, W3};
    int n = blockIdx.x * blockDim.x + threadIdx.x;   // 0..2097151
    int p  = n & 1;
    int c  = (n >> 1) & 3;
    int nn = (n >> 3) & 127;
    int ch = (n >> 10) & 63;
    int cb = (n >> 16) & 7;
    int g  = n >> 19;
    int col = cb * 128 + nn;
    int k   = ch * 16 + 2 * c + 8 * p;
    g_Wx16[n] = pack2h(W[g][(size_t)k * HH + col],
                       W[g][(size_t)(k + 1) * HH + col]);
}

__global__ __launch_bounds__(256) void pack_why(const float* __restrict__ Why) {
    int n = blockIdx.x * blockDim.x + threadIdx.x;   // 0..524287
    int p  = n & 1;
    int c  = (n >> 1) & 3;
    int nn = (n >> 3) & 127;
    int ch = (n >> 10) & 63;
    int cb = n >> 16;
    int col = cb * 128 + nn;
    int k   = ch * 16 + 2 * c + 8 * p;
    g_Why16[n] = pack2h(Why[(size_t)k * HH + col],
                        Why[(size_t)(k + 1) * HH + col]);
}

// ---------------- big fp16 GEMM, cp.async 3-stage ----------------------------
// C[M,1024] = A@B + bias. A,B globally pre-packed in fragment order.
// 128x128 tile, BK=64 (4 k16-chunks), 16 iters, 256 thr (8 warps: 2m x 4n).
// Stage = 4096 u32 each for A and B; smem 3*(16+16)KB = 96KB.
#define GSTG 4096
#define GST 3

__device__ __forceinline__ void gemm_f16_core(
    const uint32_t* __restrict__ A, const uint32_t* __restrict__ Bw,
    const float* __restrict__ bias, float* __restrict__ C)
{
    extern __shared__ __align__(16) uint32_t gsm[];
    uint32_t* Asm = gsm;                 // 3 * 4096
    uint32_t* Bsm = gsm + GST * GSTG;    // 3 * 4096

    const int tid  = threadIdx.x;
    const int lane = tid & 31;
    const int w    = tid >> 5;
    const int wm   = w & 1;
    const int wn   = w >> 1;

    const uint32_t* Ab = A  + (size_t)blockIdx.y * 65536;   // mtile base
    const uint32_t* Bb = Bw + (size_t)blockIdx.x * 65536;   // colblock base
    const int m0 = blockIdx.y * 128;
    const int n0 = blockIdx.x * 128;

    const uint32_t sA = (uint32_t)__cvta_generic_to_shared(Asm);
    const uint32_t sB = (uint32_t)__cvta_generic_to_shared(Bsm);

    float acc[4][4][4];
    #pragma unroll
    for (int i = 0; i < 4; ++i)
        #pragma unroll
        for (int j = 0; j < 4; ++j)
            #pragma unroll
            for (int r = 0; r < 4; ++r) acc[i][j][r] = 0.0f;

    auto issue = [&](int it, int slot) {
        const uint32_t* As = Ab + it * GSTG;
        const uint32_t* Bs = Bb + it * GSTG;
        #pragma unroll
        for (int j = 0; j < 4; ++j) {
            int idx = (tid + 256 * j) * 4;
            cp_async16(sA + (slot * GSTG + idx) * 4, As + idx);
            cp_async16(sB + (slot * GSTG + idx) * 4, Bs + idx);
        }
    };

    issue(0, 0); cp_commit();
    issue(1, 1); cp_commit();

    const int arow = wm * 64 + (lane >> 2);
    const int acp  = (lane & 3) * 2;

    for (int it = 0; it < 16; ++it) {
        cp_wait<1>();
        __syncthreads();
        if (it + 2 < 16) issue(it + 2, (it + 2) % GST);
        cp_commit();

        const uint32_t* As = Asm + (it % GST) * GSTG;
        const uint32_t* Bs = Bsm + (it % GST) * GSTG;

        #pragma unroll
        for (int ch = 0; ch < 4; ++ch) {
            uint2 afa[4], afb[4];
            #pragma unroll
            for (int mt = 0; mt < 4; ++mt) {
                int base = (ch * 128 + arow + mt * 16) * 8 + acp;
                afa[mt] = *(const uint2*)(As + base);        // a0, a2
                afb[mt] = *(const uint2*)(As + base + 64);   // a1, a3 (row+8)
            }
            uint2 bf[4];
            #pragma unroll
            for (int nt = 0; nt < 4; ++nt) {
                int nb = (ch * 128 + wn * 32 + nt * 8 + (lane >> 2)) * 8 + acp;
                bf[nt] = *(const uint2*)(Bs + nb);           // b0, b1
            }
            #pragma unroll
            for (int mt = 0; mt < 4; ++mt)
                #pragma unroll
                for (int nt = 0; nt < 4; ++nt)
                    mma_f16(acc[mt][nt], afa[mt].x, afb[mt].x,
                            afa[mt].y, afb[mt].y, bf[nt].x, bf[nt].y);
        }
    }

    #pragma unroll
    for (int mt = 0; mt < 4; ++mt) {
        int row = m0 + wm * 64 + mt * 16 + (lane >> 2);
        #pragma unroll
        for (int nt = 0; nt < 4; ++nt) {
            int col = n0 + wn * 32 + nt * 8 + 2 * (lane & 3);
            float b0 = bias[col], b1 = bias[col + 1];
            float2 v0 = {acc[mt][nt][0] + b0, acc[mt][nt][1] + b1};
            float2 v1 = {acc[mt][nt][2] + b0, acc[mt][nt][3] + b1};
            *(float2*)&C[(size_t)row * HH + col]       = v0;
            *(float2*)&C[(size_t)(row + 8) * HH + col] = v1;
        }
    }
}

__global__ __launch_bounds__(256) void gemm_xproj_f16(
    const float* __restrict__ b0, const float* __restrict__ b1,
    const float* __restrict__ b2, const float* __restrict__ b3)
{
    const float* bs[4] = {b0, b1, b2, b3};
    int g = blockIdx.z;
    gemm_f16_core(g_X16, g_Wx16 + (size_t)g * 524288, bs[g],
                  g_XP + (size_t)g * SB * HH);
}

__global__ __launch_bounds__(256) void gemm_outproj_f16(
    const float* __restrict__ bias, float* __restrict__ out)
{
    gemm_f16_core(g_Hl16, g_Why16, bias, out);
}

// ---------------- Persistent recurrence kernel (fp16 MMA, R13-proven) --------
#define PST 6
#define PNIT 16
#define REDW 2176   // 64*34

__global__ __launch_bounds__(512) void lstm_persist(
    const float* __restrict__ bi, const float* __restrict__ bf,
    const float* __restrict__ bc, const float* __restrict__ bo)
{
    extern __shared__ __align__(16) uint32_t smu[];
    uint32_t* Wsm16 = smu;                         // 16384 u32 (64KB)
    uint32_t* Asm32 = smu + 16384;                 // 6*2048 u32 (48KB, alias red)
    float*    XPsm  = (float*)(smu + 16384 + PST * 2048);  // 2*2048 f
    float*    pre   = XPsm + 4096;                 // 2176 f
    float*    red   = (float*)Asm32;               // red[3][64][34]

    const int tid  = threadIdx.x;
    const int lane = tid & 31;
    const int w    = tid >> 5;
    const int wm   = w & 3;
    const int wk   = w >> 2;
    const int bx   = blockIdx.x;
    const int c0   = bx * 8;

    const uint32_t sW = (uint32_t)__cvta_generic_to_shared(Wsm16);
    const uint32_t sA = (uint32_t)__cvta_generic_to_shared(Asm32);
    const uint32_t sX = (uint32_t)__cvta_generic_to_shared(XPsm);

    // ---- load fp16 weights once ----
    {
        const uint32_t* Wsrc = g_Wpk16 + (size_t)bx * 16384;
        #pragma unroll 4
        for (int j = 0; j < 8; ++j) {
            int idx = tid + 512 * j;
            cp_async16(sW + idx * 16, Wsrc + idx * 4);
        }
    }
    // ---- XP prefetch for step 0 ----
    {
        int gate = tid >> 7, r2 = (tid >> 1) & 63, half = tid & 1;
        const float* src = g_XP + (size_t)gate * SB * HH
                         + (size_t)r2 * HH + c0 + half * 4;
        cp_async16(sX + (gate * 512 + r2 * 8 + half * 4) * 4, src);
    }
    cp_commit();

    const int cc  = tid & 7;
    const int col = c0 + cc;
    const int row = tid >> 3;            // 0..63
    const float bI = bi[col], bF = bf[col], bC = bc[col], bO = bo[col];
    // fp16-packed h write (recurrence buffer): col -> (chunk,c,p,d)
    const int hchunk = col >> 4;
    const int hkk    = col & 15;
    const int hp     = hkk >> 3;
    const int hc     = (hkk & 7) >> 1;
    const int hd     = hkk & 1;
    const int hidx   = ((hchunk * 64 + row) * 4 + hc) * 4 + hp * 2 + hd;  // half idx
    float creg = 0.0f;

    const int aoff = ((wm * 16 + (lane >> 2)) * 4 + (lane & 3)) * 2 + wk * 512;
    const int nrow = lane >> 2;
    const int bcc  = lane & 3;

    for (int t = 0; t < SS; ++t) {
        const uint32_t* Asrc = g_HTp16[t & 1];
        uint16_t*       hTn  = (uint16_t*)g_HTp16[(t + 1) & 1];
        // packed Hall write for outproj: global row R = t*64+row
        // half idx = (((mt*64+ch)*128+row128)*8 + c*2 + p)*2 + d
        uint16_t* hAll = (uint16_t*)g_Hl16;
        const int mt128   = t >> 1;
        const int row128  = ((t & 1) << 6) + row;
        const size_t hallidx = ((((size_t)mt128 * 64 + hchunk) * 128 + row128) * 8
                                + hc * 2 + hp) * 2 + hd;

        float acc[4][4];
        #pragma unroll
        for (int nt = 0; nt < 4; ++nt)
            #pragma unroll
            for (int r = 0; r < 4; ++r) acc[nt][r] = 0.0f;

        #pragma unroll
        for (int i = 0; i < PST - 1; ++i) {
            cp_async16(sA + ((i % PST) * 2048 + tid * 4) * 4,
                       Asrc + i * 2048 + tid * 4);
            cp_commit();
        }

        for (int it = 0; it < PNIT; ++it) {
            cp_wait<PST - 2>();
            __syncthreads();
            if (it + PST - 1 < PNIT) {
                int i = it + PST - 1;
                cp_async16(sA + ((i % PST) * 2048 + tid * 4) * 4,
                           Asrc + i * 2048 + tid * 4);
            }
            if (it == 0 && t + 1 < SS) {
                int buf  = (t + 1) & 1;
                int gate = tid >> 7, r2 = (tid >> 1) & 63, half = tid & 1;
                const float* src = g_XP + (size_t)gate * SB * HH
                                 + ((size_t)(t + 1) * BB + r2) * HH + c0 + half * 4;
                cp_async16(sX + (buf * 2048 + gate * 512 + r2 * 8 + half * 4) * 4, src);
            }
            cp_commit();

            const uint32_t* Asl = Asm32 + (it % PST) * 2048;
            const int chunk = it * 4 + wk;

            uint2 a01 = *(const uint2*)(Asl + aoff);
            uint2 a23 = *(const uint2*)(Asl + aoff + 64);
            #pragma unroll
            for (int nt = 0; nt < 4; ++nt) {
                const uint32_t* Bb = Wsm16 + ((chunk * 32 + nt * 8 + nrow) * 4 + bcc) * 2;
                uint2 b = *(const uint2*)Bb;
                mma_f16(acc[nt], a01.x, a23.x, a01.y, a23.y, b.x, b.y);
            }
        }

        cp_wait<0>();
        __syncthreads();

        if (wk > 0) {
            #pragma unroll
            for (int nt = 0; nt < 4; ++nt) {
                int r0 = wm * 16 + (lane >> 2);
                int cr = nt * 8 + 2 * (lane & 3);
                *(float2*)&red[(wk - 1) * REDW + r0 * 34 + cr]
                    = make_float2(acc[nt][0], acc[nt][1]);
                *(float2*)&red[(wk - 1) * REDW + (r0 + 8) * 34 + cr]
                    = make_float2(acc[nt][2], acc[nt][3]);
            }
        }
        __syncthreads();
        if (wk == 0) {
            #pragma unroll
            for (int nt = 0; nt < 4; ++nt) {
                int r0 = wm * 16 + (lane >> 2);
                int cr = nt * 8 + 2 * (lane & 3);
                float2 s0 = make_float2(acc[nt][0], acc[nt][1]);
                float2 s1 = make_float2(acc[nt][2], acc[nt][3]);
                #pragma unroll
                for (int p = 0; p < 3; ++p) {
                    float2 u0 = *(const float2*)&red[p * REDW + r0 * 34 + cr];
                    float2 u1 = *(const float2*)&red[p * REDW + (r0 + 8) * 34 + cr];
                    s0.x += u0.x; s0.y += u0.y;
                    s1.x += u1.x; s1.y += u1.y;
                }
                *(float2*)&pre[r0 * 34 + cr]       = s0;
                *(float2*)&pre[(r0 + 8) * 34 + cr] = s1;
            }
        }
        __syncthreads();

        const float* xp = XPsm + (t & 1) * 2048;
        {
            int b0 = row * 34 + cc;

            float pi = pre[b0]      + xp[0 * 512 + row * 8 + cc] + bI;
            float pf = pre[b0 + 8]  + xp[1 * 512 + row * 8 + cc] + bF;
            float pc = pre[b0 + 16] + xp[2 * 512 + row * 8 + cc] + bC;
            float po = pre[b0 + 24] + xp[3 * 512 + row * 8 + cc] + bO;

            float iv = 1.0f / (1.0f + expf(-pi));
            float fv = 1.0f / (1.0f + expf(-pf));
            float ov = 1.0f / (1.0f + expf(-po));
            float gv = tanhf(pc);

            float cv = fv * creg + iv * gv;
            float hv = ov * tanhf(cv);
            creg = cv;

            uint16_t h16 = __half_as_ushort(__float2half(hv));
            hTn[hidx]     = h16;   // recurrence A buffer
            hAll[hallidx] = h16;   // outproj A buffer (packed)
        }

        if (t + 1 < SS) {
            __threadfence();
            __syncthreads();
            if (tid == 0) {
                atomicAdd(&g_bar, 1u);
                unsigned need = 128u * (unsigned)(t + 1);
                while (*((volatile unsigned*)&g_bar) < need) { __nanosleep(16); }
            }
            __syncthreads();
        }
    }
}

// ---------------- launch -----------------------------------------------------
extern "C" void kernel_launch(void* const* d_in, const int* in_sizes, int n_in,
                              void* d_out, int out_size)
{
    (void)in_sizes; (void)n_in; (void)out_size;

    const float* x    = (const float*)d_in[0];
    const float* Wx[4] = {(const float*)d_in[1], (const float*)d_in[3],
                          (const float*)d_in[5], (const float*)d_in[7]};
    const float* bx[4] = {(const float*)d_in[2], (const float*)d_in[4],
                          (const float*)d_in[6], (const float*)d_in[8]};
    const float* Wh[4] = {(const float*)d_in[9],  (const float*)d_in[11],
                          (const float*)d_in[13], (const float*)d_in[15]};
    const float* bh[4] = {(const float*)d_in[10], (const float*)d_in[12],
                          (const float*)d_in[14], (const float*)d_in[16]};
    const float* Why = (const float*)d_in[17];
    const float* bhy = (const float*)d_in[18];
    float* out = (float*)d_out;

    static int smem_set = 0;
    const int psmem = (16384 + PST * 2048 + 2 * 2048 + REDW) * 4;
    const int gsmem = GST * 2 * GSTG * 4;   // 96KB
    if (!smem_set) {
        cudaFuncSetAttribute(lstm_persist,
                             cudaFuncAttributeMaxDynamicSharedMemorySize, psmem);
        cudaFuncSetAttribute(gemm_xproj_f16,
                             cudaFuncAttributeMaxDynamicSharedMemorySize, gsmem);
        cudaFuncSetAttribute(gemm_outproj_f16,
                             cudaFuncAttributeMaxDynamicSharedMemorySize, gsmem);
        smem_set = 1;
    }

    init_state_kernel<<<(32768 + 256) / 256, 256>>>();
    repack_w16<<<2097152 / 256, 256>>>(Wh[0], Wh[1], Wh[2], Wh[3]);
    pack_x<<<16777216 / 256, 256>>>(x);
    pack_wx<<<2097152 / 256, 256>>>(Wx[0], Wx[1], Wx[2], Wx[3]);
    pack_why<<<524288 / 256, 256>>>(Why);

    // input projections: XP[g] = x @ W_x[g] + b_x[g]
    {
        dim3 grid(8, 256, 4);
        gemm_xproj_f16<<<grid, 256, gsmem>>>(bx[0], bx[1], bx[2], bx[3]);
    }

    lstm_persist<<<128, 512, psmem>>>(bh[0], bh[1], bh[2], bh[3]);

    // output projection: Y = H_all @ W_hy + b_hy
    {
        dim3 grid(8, 256);
        gemm_outproj_f16<<<grid, 256, gsmem>>>(bhy, out);
    }
}